// round 1
// baseline (speedup 1.0000x reference)
#include <cuda_runtime.h>
#include <math.h>

#define Bdim 4
#define Sdim 2048
#define Ddim 768
#define Edim 8
#define TOPK 2
#define Hdim 3072
#define NTOK (Bdim * Sdim)        // 8192 tokens
#define NDISP (NTOK * TOPK)       // 16384 dispatch rows (exact, every token picks 2)

// ---------------- scratch (static device allocations; no cudaMalloc) ----------
__device__ int   g_cnt[Edim];
__device__ int   g_off[Edim];
__device__ int   g_cur[Edim];
__device__ int   g_top_e[NTOK * TOPK];
__device__ float g_top_g[NTOK * TOPK];
__device__ int   g_tok[NDISP];          // dispatch row -> token id
__device__ float g_gate[NDISP];         // dispatch row -> gate
__device__ int   g_pos[NTOK * TOPK];    // (token, slot) -> dispatch row
__device__ float g_h[(size_t)NDISP * Hdim];   // 201 MB intermediate activations
__device__ float g_yd[(size_t)NDISP * Ddim];  // 50 MB per-dispatch outputs (gate applied)

// ---------------- kernel 0: zero the counters ---------------------------------
__global__ void zero_kernel() {
    int t = threadIdx.x;
    if (t < Edim) g_cnt[t] = 0;
}

// ---------------- kernel 1: router (1 warp per token) --------------------------
__global__ void router_kernel(const float* __restrict__ x,
                              const float* __restrict__ noise,
                              const float* __restrict__ w_route,
                              const float* __restrict__ b_route,
                              const float* __restrict__ w_noise,
                              const float* __restrict__ b_noise) {
    int warp = (blockIdx.x * blockDim.x + threadIdx.x) >> 5;
    int lane = threadIdx.x & 31;
    if (warp >= NTOK) return;

    const float* xr = x + (size_t)warp * Ddim;
    float ar[Edim], an[Edim];
#pragma unroll
    for (int e = 0; e < Edim; e++) { ar[e] = 0.f; an[e] = 0.f; }

    for (int k = lane; k < Ddim; k += 32) {
        float xv = xr[k];
        const float* wr = w_route + (size_t)k * Edim;
        const float* wn = w_noise + (size_t)k * Edim;
#pragma unroll
        for (int e = 0; e < Edim; e++) {
            ar[e] += xv * wr[e];
            an[e] += xv * wn[e];
        }
    }
#pragma unroll
    for (int e = 0; e < Edim; e++) {
#pragma unroll
        for (int o = 16; o > 0; o >>= 1) {
            ar[e] += __shfl_down_sync(0xffffffffu, ar[e], o);
            an[e] += __shfl_down_sync(0xffffffffu, an[e], o);
        }
    }

    if (lane == 0) {
        float nv[Edim];
#pragma unroll
        for (int e = 0; e < Edim; e++) {
            float z = an[e] + b_noise[e];
            float sp = (z > 0.f) ? (z + log1pf(expf(-z))) : log1pf(expf(z));
            nv[e] = ar[e] + b_route[e] + noise[(size_t)warp * Edim + e] * sp;
        }
        // top-2, tie-break = lowest index first (matches jax.lax.top_k)
        int i1 = 0;
#pragma unroll
        for (int e = 1; e < Edim; e++) if (nv[e] > nv[i1]) i1 = e;
        int i2 = -1;
#pragma unroll
        for (int e = 0; e < Edim; e++) {
            if (e == i1) continue;
            if (i2 < 0 || nv[e] > nv[i2]) i2 = e;
        }
        // softmax over {nv[i1], nv[i2]} (others -inf)
        float d  = nv[i2] - nv[i1];         // <= 0
        float ex = expf(d);
        float g1 = 1.f / (1.f + ex);
        float g2 = ex / (1.f + ex);

        g_top_e[warp * 2 + 0] = i1;  g_top_g[warp * 2 + 0] = g1;
        g_top_e[warp * 2 + 1] = i2;  g_top_g[warp * 2 + 1] = g2;
        atomicAdd(&g_cnt[i1], 1);
        atomicAdd(&g_cnt[i2], 1);
    }
}

// ---------------- kernel 2: exclusive prefix scan over 8 experts ---------------
__global__ void scan_kernel() {
    if (threadIdx.x == 0) {
        int acc = 0;
        for (int e = 0; e < Edim; e++) {
            g_off[e] = acc;
            g_cur[e] = acc;
            acc += g_cnt[e];
        }
    }
}

// ---------------- kernel 3: fill compact dispatch lists ------------------------
__global__ void fill_kernel() {
    int idx = blockIdx.x * blockDim.x + threadIdx.x;
    if (idx >= NDISP) return;
    int t = idx >> 1;
    int e = g_top_e[idx];
    int pos = atomicAdd(&g_cur[e], 1);
    g_tok[pos]  = t;
    g_gate[pos] = g_top_g[idx];
    g_pos[idx]  = pos;
}

// ---------------- kernel 4: GEMM1  h = relu(X_gathered @ W1[e] + b1[e]) --------
// 128x128 tile, K-step 8, 256 threads, 8x8 per-thread micro-tile.
__global__ void __launch_bounds__(256, 2)
ffn1_kernel(const float* __restrict__ x,
            const float* __restrict__ W1,
            const float* __restrict__ b1) {
    int e = blockIdx.z;
    int cnt = g_cnt[e];
    int m0 = blockIdx.y * 128;
    if (m0 >= cnt) return;
    int base = g_off[e];
    int n0 = blockIdx.x * 128;
    const float* Bp = W1 + (size_t)e * Ddim * Hdim;

    __shared__ float As[8][132];
    __shared__ float Bs[8][128];
    __shared__ int rows[128];

    int tid = threadIdx.x;
    if (tid < 128) {
        int r = m0 + tid;
        rows[tid] = (r < cnt) ? g_tok[base + r] : -1;
    }
    __syncthreads();

    int arow = tid >> 1, akc = (tid & 1) * 4;
    int bkr = tid >> 5, bnc = (tid & 31) * 4;
    int tm = (tid >> 4) * 8, tn = (tid & 15) * 8;

    float acc[8][8];
#pragma unroll
    for (int i = 0; i < 8; i++)
#pragma unroll
        for (int j = 0; j < 8; j++) acc[i][j] = 0.f;

    int trow = rows[arow];
    const float* ap_base = (trow >= 0) ? (x + (size_t)trow * Ddim + akc) : nullptr;

    for (int k0 = 0; k0 < Ddim; k0 += 8) {
        float4 av = make_float4(0.f, 0.f, 0.f, 0.f);
        if (ap_base) av = *(const float4*)(ap_base + k0);
        float4 bv = *(const float4*)(Bp + (size_t)(k0 + bkr) * Hdim + n0 + bnc);

        __syncthreads();
        As[akc + 0][arow] = av.x;
        As[akc + 1][arow] = av.y;
        As[akc + 2][arow] = av.z;
        As[akc + 3][arow] = av.w;
        *(float4*)&Bs[bkr][bnc] = bv;
        __syncthreads();

#pragma unroll
        for (int kk = 0; kk < 8; kk++) {
            float4 aA = *(const float4*)&As[kk][tm];
            float4 aB = *(const float4*)&As[kk][tm + 4];
            float4 bA = *(const float4*)&Bs[kk][tn];
            float4 bB = *(const float4*)&Bs[kk][tn + 4];
            float a[8] = {aA.x, aA.y, aA.z, aA.w, aB.x, aB.y, aB.z, aB.w};
            float b[8] = {bA.x, bA.y, bA.z, bA.w, bB.x, bB.y, bB.z, bB.w};
#pragma unroll
            for (int i = 0; i < 8; i++)
#pragma unroll
                for (int j = 0; j < 8; j++) acc[i][j] += a[i] * b[j];
        }
    }

    const float* b1p = b1 + (size_t)e * Hdim + n0 + tn;
#pragma unroll
    for (int i = 0; i < 8; i++) {
        int r = m0 + tm + i;
        if (r < cnt) {
            float* hp = g_h + (size_t)(base + r) * Hdim + n0 + tn;
#pragma unroll
            for (int j = 0; j < 8; j++)
                hp[j] = fmaxf(acc[i][j] + b1p[j], 0.f);
        }
    }
}

// ---------------- kernel 5: GEMM2  yd = gate * (h @ W2[e] + b2[e]) -------------
__global__ void __launch_bounds__(256, 2)
ffn2_kernel(const float* __restrict__ W2,
            const float* __restrict__ b2) {
    int e = blockIdx.z;
    int cnt = g_cnt[e];
    int m0 = blockIdx.y * 128;
    if (m0 >= cnt) return;
    int base = g_off[e];
    int n0 = blockIdx.x * 128;
    const float* Bp = W2 + (size_t)e * Hdim * Ddim;

    __shared__ float As[8][132];
    __shared__ float Bs[8][128];

    int tid = threadIdx.x;
    int arow = tid >> 1, akc = (tid & 1) * 4;
    int bkr = tid >> 5, bnc = (tid & 31) * 4;
    int tm = (tid >> 4) * 8, tn = (tid & 15) * 8;

    int r_a = m0 + arow;
    bool aval = (r_a < cnt);
    const float* ap_base = g_h + (size_t)(base + r_a) * Hdim + akc;

    float acc[8][8];
#pragma unroll
    for (int i = 0; i < 8; i++)
#pragma unroll
        for (int j = 0; j < 8; j++) acc[i][j] = 0.f;

    for (int k0 = 0; k0 < Hdim; k0 += 8) {
        float4 av = make_float4(0.f, 0.f, 0.f, 0.f);
        if (aval) av = *(const float4*)(ap_base + k0);
        float4 bv = *(const float4*)(Bp + (size_t)(k0 + bkr) * Ddim + n0 + bnc);

        __syncthreads();
        As[akc + 0][arow] = av.x;
        As[akc + 1][arow] = av.y;
        As[akc + 2][arow] = av.z;
        As[akc + 3][arow] = av.w;
        *(float4*)&Bs[bkr][bnc] = bv;
        __syncthreads();

#pragma unroll
        for (int kk = 0; kk < 8; kk++) {
            float4 aA = *(const float4*)&As[kk][tm];
            float4 aB = *(const float4*)&As[kk][tm + 4];
            float4 bA = *(const float4*)&Bs[kk][tn];
            float4 bB = *(const float4*)&Bs[kk][tn + 4];
            float a[8] = {aA.x, aA.y, aA.z, aA.w, aB.x, aB.y, aB.z, aB.w};
            float b[8] = {bA.x, bA.y, bA.z, bA.w, bB.x, bB.y, bB.z, bB.w};
#pragma unroll
            for (int i = 0; i < 8; i++)
#pragma unroll
                for (int j = 0; j < 8; j++) acc[i][j] += a[i] * b[j];
        }
    }

    const float* b2p = b2 + (size_t)e * Ddim + n0 + tn;
#pragma unroll
    for (int i = 0; i < 8; i++) {
        int r = m0 + tm + i;
        if (r < cnt) {
            float g = g_gate[base + r];
            float* yp = g_yd + (size_t)(base + r) * Ddim + n0 + tn;
#pragma unroll
            for (int j = 0; j < 8; j++)
                yp[j] = g * (acc[i][j] + b2p[j]);
        }
    }
}

// ---------------- kernel 6: combine the two expert contributions ---------------
__global__ void combine_kernel(float* __restrict__ out) {
    int idx = blockIdx.x * blockDim.x + threadIdx.x;  // in float4 units
    int total = NTOK * Ddim / 4;
    if (idx >= total) return;
    int t = idx / (Ddim / 4);
    int d4 = idx % (Ddim / 4);
    int p0 = g_pos[t * 2 + 0];
    int p1 = g_pos[t * 2 + 1];
    float4 a = *(const float4*)(g_yd + (size_t)p0 * Ddim + d4 * 4);
    float4 b = *(const float4*)(g_yd + (size_t)p1 * Ddim + d4 * 4);
    float4 o;
    o.x = a.x + b.x; o.y = a.y + b.y; o.z = a.z + b.z; o.w = a.w + b.w;
    *(float4*)(out + (size_t)t * Ddim + d4 * 4) = o;
}

// ---------------- launch -------------------------------------------------------
extern "C" void kernel_launch(void* const* d_in, const int* in_sizes, int n_in,
                              void* d_out, int out_size) {
    const float* x       = (const float*)d_in[0];
    const float* noise   = (const float*)d_in[1];
    const float* w_route = (const float*)d_in[2];
    const float* b_route = (const float*)d_in[3];
    const float* w_noise = (const float*)d_in[4];
    const float* b_noise = (const float*)d_in[5];
    const float* W1      = (const float*)d_in[6];
    const float* b1      = (const float*)d_in[7];
    const float* W2      = (const float*)d_in[8];
    const float* b2      = (const float*)d_in[9];
    float* out = (float*)d_out;

    zero_kernel<<<1, 32>>>();
    router_kernel<<<NTOK / 8, 256>>>(x, noise, w_route, b_route, w_noise, b_noise);
    scan_kernel<<<1, 1>>>();
    fill_kernel<<<(NDISP + 255) / 256, 256>>>();
    ffn1_kernel<<<dim3(Hdim / 128, NTOK / 128, Edim), 256>>>(x, W1, b1);
    ffn2_kernel<<<dim3(Ddim / 128, NTOK / 128, Edim), 256>>>(W2, b2);
    combine_kernel<<<(NTOK * Ddim / 4 + 255) / 256, 256>>>(out);
}